// round 12
// baseline (speedup 1.0000x reference)
#include <cuda_runtime.h>
#include <math.h>

#define D_INNER 8192
#define D_MODEL 4096
#define DT_RANK 8
#define D_STATE 16
#define XP_ROWS (DT_RANK + 2 * D_STATE)  // 40

// Role layout in one grid (bid-ordered so producers schedule first)
#define NB_K1   8192                     // 2 rows/block: rows [0, 16384)
#define NB_XP   XP_ROWS                  // 1 xp row/block
#define NB_SSM  64                       // 128 ssm rows/block
#define NB_K4   4096                     // 1 out row/block
#define B_XP    (NB_K1)
#define B_SSM   (NB_K1 + NB_XP)
#define B_K4    (NB_K1 + NB_XP + NB_SSM)
#define NB_ALL  (NB_K1 + NB_XP + NB_SSM + NB_K4)

// Scratch (allocation-free rule: __device__ globals)
__device__ float g_z[D_INNER];
__device__ float g_xconv[D_INNER];
__device__ float g_xp[XP_ROWS];
__device__ float g_y[D_INNER];

// Dataflow counters (self-resetting at end of each run)
__device__ int c_xconv = 0;   // -> 4096 (K1 blocks with rows < 8192)
__device__ int c_z     = 0;   // -> 4096 (K1 blocks with rows >= 8192)
__device__ int c_xp    = 0;   // -> 40
__device__ int c_y     = 0;   // -> 64
__device__ int c_done  = 0;   // -> NB_K4, triggers reset

__device__ __forceinline__ float silu_fast(float v) {
    return v / (1.0f + __expf(-v));
}

__device__ __forceinline__ float dot4(float4 w, float4 v) {
    return w.x * v.x + w.y * v.y + w.z * v.z + w.w * v.w;
}

// Per-warp streaming partial dot over a contiguous region of len4 float4.
__device__ __forceinline__ float partial_dot(const float4* __restrict__ Wr,
                                             const float4* __restrict__ xv,
                                             int lane, int len4) {
    float acc0 = 0.f, acc1 = 0.f, acc2 = 0.f, acc3 = 0.f;
    #pragma unroll
    for (int i = lane; i < len4; i += 128) {
        float4 w0 = __ldcs(&Wr[i]);
        float4 w1 = __ldcs(&Wr[i + 32]);
        float4 w2 = __ldcs(&Wr[i + 64]);
        float4 w3 = __ldcs(&Wr[i + 96]);
        float4 v0 = xv[i], v1 = xv[i + 32], v2 = xv[i + 64], v3 = xv[i + 96];
        acc0 += dot4(w0, v0);
        acc1 += dot4(w1, v1);
        acc2 += dot4(w2, v2);
        acc3 += dot4(w3, v3);
    }
    float acc = (acc0 + acc1) + (acc2 + acc3);
    #pragma unroll
    for (int o = 16; o; o >>= 1) acc += __shfl_xor_sync(0xffffffffu, acc, o);
    return acc;
}

// Block-wide acquire-wait: ctr >= target.
__device__ __forceinline__ void block_wait(int* ctr, int target) {
    if (threadIdx.x == 0) {
        volatile int* vc = (volatile int*)ctr;
        while (*vc < target) __nanosleep(128);
    }
    __syncthreads();
    __threadfence();
}

// Block-wide release: all prior stores visible, then bump counter.
__device__ __forceinline__ void block_release(int* ctr) {
    __syncthreads();
    __threadfence();
    if (threadIdx.x == 0) atomicAdd(ctr, 1);
}

// ---------------------------------------------------------------------------
// Mega-kernel: all four stages, dataflow-synced, one launch.
// ---------------------------------------------------------------------------
__global__ __launch_bounds__(128) void ssm_mega(
    const float* __restrict__ x,
    const float* __restrict__ ssm_state,
    const float* __restrict__ conv_buffer,
    const float* __restrict__ W_in,
    const float* __restrict__ conv_w,
    const float* __restrict__ conv_b,
    const float* __restrict__ W_xp,
    const float* __restrict__ W_dt,
    const float* __restrict__ b_dt,
    const float* __restrict__ A_log,
    const float* __restrict__ D_param,
    const float* __restrict__ W_out,
    float* __restrict__ out,
    float* __restrict__ new_h_out) {
    const int b    = blockIdx.x;
    const int tid  = threadIdx.x;
    const int wid  = tid >> 5;
    const int lane = tid & 31;
    __shared__ float part[4];
    __shared__ float s_xp[XP_ROWS];

    if (b < NB_K1) {
        // ---- K1: xz rows [2b, 2b+1]; warp w: row 2b+(w>>1), half w&1 ----
        int row  = 2 * b + (wid >> 1);
        int half = wid & 1;
        const int h4 = D_MODEL / 8;  // 512 float4 per half-row
        const float4* Wr = reinterpret_cast<const float4*>(W_in + (size_t)row * D_MODEL)
                         + half * h4;
        const float4* xv = reinterpret_cast<const float4*>(x) + half * h4;
        float acc = partial_dot(Wr, xv, lane, h4);
        if (lane == 0) part[wid] = acc;
        __syncthreads();
        if (tid < 2) {
            int r = 2 * b + tid;
            float s = part[2 * tid] + part[2 * tid + 1];
            if (r < D_INNER) {
                float b1 = conv_buffer[r * 3 + 1];
                float b2 = conv_buffer[r * 3 + 2];
                float4 w = reinterpret_cast<const float4*>(conv_w)[r];
                float cs = b1 * w.x + b2 * w.y + s * (w.z + w.w) + conv_b[r];
                g_xconv[r] = silu_fast(cs);
            } else {
                g_z[r - D_INNER] = s;
            }
        }
        block_release(b < NB_K1 / 2 ? &c_xconv : &c_z);

    } else if (b < B_SSM) {
        // ---- K2: xp row (b - B_XP); warp w: quarter-row ----
        block_wait(&c_xconv, NB_K1 / 2);
        int row = b - B_XP;
        const int q4 = D_INNER / 16;  // 512 float4 per quarter-row
        const float4* Wr = reinterpret_cast<const float4*>(W_xp + (size_t)row * D_INNER)
                         + wid * q4;
        const float4* xv = reinterpret_cast<const float4*>(g_xconv) + wid * q4;
        float acc = partial_dot(Wr, xv, lane, q4);
        if (lane == 0) part[wid] = acc;
        __syncthreads();
        if (tid == 0) g_xp[row] = (part[0] + part[1]) + (part[2] + part[3]);
        block_release(&c_xp);

    } else if (b < B_K4) {
        // ---- K3: ssm update, 128 rows per block ----
        block_wait(&c_xp, NB_XP);        // implies xconv complete
        if (tid == 0) {
            volatile int* vc = (volatile int*)&c_z;
            while (*vc < NB_K1 / 2) __nanosleep(128);
        }
        __syncthreads();
        __threadfence();

        if (tid < XP_ROWS) s_xp[tid] = g_xp[tid];
        __syncthreads();

        int i = (b - B_SSM) * 128 + tid;

        const float4* wd = reinterpret_cast<const float4*>(W_dt + (size_t)i * DT_RANK);
        float4 w0 = wd[0], w1 = wd[1];
        float acc = b_dt[i]
            + w0.x * s_xp[0] + w0.y * s_xp[1] + w0.z * s_xp[2] + w0.w * s_xp[3]
            + w1.x * s_xp[4] + w1.y * s_xp[5] + w1.z * s_xp[6] + w1.w * s_xp[7];
        float dt = fmaxf(acc, 0.0f) + log1pf(__expf(-fabsf(acc)));

        float xc  = g_xconv[i];
        float dtx = dt * xc;
        const float* B = s_xp + DT_RANK;
        const float* C = s_xp + DT_RANK + D_STATE;

        const float4* Al = reinterpret_cast<const float4*>(A_log + (size_t)i * D_STATE);
        const float4* Hs = reinterpret_cast<const float4*>(ssm_state + (size_t)i * D_STATE);
        float4* Ho = reinterpret_cast<float4*>(new_h_out + (size_t)i * D_STATE);

        float ysum = 0.0f;
        #pragma unroll
        for (int q = 0; q < 4; q++) {
            float4 a4 = Al[q];
            float4 h4 = Hs[q];
            float4 o4;
            o4.x = __expf(-dt * __expf(a4.x)) * h4.x + dtx * B[4 * q + 0];
            o4.y = __expf(-dt * __expf(a4.y)) * h4.y + dtx * B[4 * q + 1];
            o4.z = __expf(-dt * __expf(a4.z)) * h4.z + dtx * B[4 * q + 2];
            o4.w = __expf(-dt * __expf(a4.w)) * h4.w + dtx * B[4 * q + 3];
            ysum += o4.x * C[4 * q + 0] + o4.y * C[4 * q + 1]
                  + o4.z * C[4 * q + 2] + o4.w * C[4 * q + 3];
            Ho[q] = o4;
        }

        float yv = ysum + D_param[i] * xc;
        g_y[i] = yv * silu_fast(g_z[i]);
        block_release(&c_y);

    } else {
        // ---- K4: out row (b - B_K4); warp w: quarter-row ----
        block_wait(&c_y, NB_SSM);
        int row = b - B_K4;
        const int q4 = D_INNER / 16;  // 512 float4 per quarter-row
        const float4* Wr = reinterpret_cast<const float4*>(W_out + (size_t)row * D_INNER)
                         + wid * q4;
        const float4* xv = reinterpret_cast<const float4*>(g_y) + wid * q4;
        float acc = partial_dot(Wr, xv, lane, q4);
        if (lane == 0) part[wid] = acc;
        __syncthreads();
        if (tid == 0) out[row] = (part[0] + part[1]) + (part[2] + part[3]);

        // completion + self-reset of counters for the next graph replay
        __threadfence();
        if (tid == 0) {
            int d = atomicAdd(&c_done, 1);
            if (d == NB_K4 - 1) {
                c_xconv = 0; c_z = 0; c_xp = 0; c_y = 0; c_done = 0;
                __threadfence();
            }
        }
    }
}

// ---------------------------------------------------------------------------
extern "C" void kernel_launch(void* const* d_in, const int* in_sizes, int n_in,
                              void* d_out, int out_size) {
    const float* x           = (const float*)d_in[0];
    const float* ssm_state   = (const float*)d_in[1];
    const float* conv_buffer = (const float*)d_in[2];
    const float* W_in        = (const float*)d_in[3];
    const float* conv_w      = (const float*)d_in[4];
    const float* conv_b      = (const float*)d_in[5];
    const float* W_xp        = (const float*)d_in[6];
    const float* W_dt        = (const float*)d_in[7];
    const float* b_dt        = (const float*)d_in[8];
    const float* A_log       = (const float*)d_in[9];
    const float* D_param     = (const float*)d_in[10];
    const float* W_out       = (const float*)d_in[11];

    float* out   = (float*)d_out;               // [0, 4096)
    float* new_h = (float*)d_out + D_MODEL;     // [4096, 4096 + 8192*16)

    ssm_mega<<<NB_ALL, 128>>>(x, ssm_state, conv_buffer, W_in, conv_w, conv_b,
                              W_xp, W_dt, b_dt, A_log, D_param, W_out,
                              out, new_h);
}

// round 13
// speedup vs baseline: 1.0924x; 1.0924x over previous
#include <cuda_runtime.h>
#include <math.h>

#define D_INNER 8192
#define D_MODEL 4096
#define DT_RANK 8
#define D_STATE 16
#define XP_ROWS (DT_RANK + 2 * D_STATE)  // 40

#define NB_SSM 64                        // ssm blocks in fused K23
#define NB_K23 (XP_ROWS + NB_SSM)        // 104 blocks: single wave

// Scratch (allocation-free rule: __device__ globals)
__device__ float g_z[D_INNER];          // z gate half of xz
__device__ float g_xconv[D_INNER];      // silu(conv(x_branch))
__device__ float g_xp[XP_ROWS];         // 40
__device__ float g_y[D_INNER];          // 8192
__device__ int   c_xp   = 0;            // xp rows completed (-> 40)
__device__ int   c_done = 0;            // ssm blocks finished (-> 64), resets

__device__ __forceinline__ float silu_fast(float v) {
    return v / (1.0f + __expf(-v));
}

__device__ __forceinline__ float dot4(float4 w, float4 v) {
    return w.x * v.x + w.y * v.y + w.z * v.z + w.w * v.w;
}

// Streaming partial dot over `len4` float4, 4-way batched, lane-strided.
__device__ __forceinline__ float partial_dot(const float4* __restrict__ Wr,
                                             const float4* __restrict__ xv,
                                             int lane, int len4) {
    float acc0 = 0.f, acc1 = 0.f, acc2 = 0.f, acc3 = 0.f;
    #pragma unroll
    for (int i = lane; i < len4; i += 128) {
        float4 w0 = __ldcs(&Wr[i]);
        float4 w1 = __ldcs(&Wr[i + 32]);
        float4 w2 = __ldcs(&Wr[i + 64]);
        float4 w3 = __ldcs(&Wr[i + 96]);
        float4 v0 = xv[i], v1 = xv[i + 32], v2 = xv[i + 64], v3 = xv[i + 96];
        acc0 += dot4(w0, v0);
        acc1 += dot4(w1, v1);
        acc2 += dot4(w2, v2);
        acc3 += dot4(w3, v3);
    }
    float acc = (acc0 + acc1) + (acc2 + acc3);
    #pragma unroll
    for (int o = 16; o; o >>= 1) acc += __shfl_xor_sync(0xffffffffu, acc, o);
    return acc;
}

// ---------------------------------------------------------------------------
// K1: xz = W_in @ x, fused conv + SiLU epilogue. (identical to R10 best)
// TWO warps per row (half-row each, 8 KB warp-task): 4096 blocks x 256 thr.
// ---------------------------------------------------------------------------
__global__ __launch_bounds__(256) void gemv_win_fused(
    const float* __restrict__ W,
    const float* __restrict__ x,
    const float* __restrict__ conv_buffer,
    const float* __restrict__ conv_w,
    const float* __restrict__ conv_b) {
    int wid  = threadIdx.x >> 5;
    int lane = threadIdx.x & 31;
    int row  = blockIdx.x * 4 + (wid >> 1);
    int half = wid & 1;
    const int h4 = D_MODEL / 8;  // 512 float4 per half-row

    const float4* Wr = reinterpret_cast<const float4*>(W + (size_t)row * D_MODEL)
                     + half * h4;
    const float4* xv = reinterpret_cast<const float4*>(x) + half * h4;

    float acc = partial_dot(Wr, xv, lane, h4);

    __shared__ float part[8];
    if (lane == 0) part[wid] = acc;
    __syncthreads();

    if (threadIdx.x < 4) {
        int r = blockIdx.x * 4 + threadIdx.x;
        float s = part[2 * threadIdx.x] + part[2 * threadIdx.x + 1];
        if (r < D_INNER) {
            float b1 = conv_buffer[r * 3 + 1];
            float b2 = conv_buffer[r * 3 + 2];
            float4 w = reinterpret_cast<const float4*>(conv_w)[r];
            float cs = b1 * w.x + b2 * w.y + s * (w.z + w.w) + conv_b[r];
            g_xconv[r] = silu_fast(cs);
        } else {
            g_z[r - D_INNER] = s;
        }
    }
}

// ---------------------------------------------------------------------------
// K23: fused xp GEMV + ssm update. 104 blocks x 128 thr = ONE wave.
// Blocks [0,40): xp row each (quarter-row per warp), release c_xp.
// Blocks [40,104): spin on c_xp==40 (64 pollers, ~1 us), then ssm rows.
// Last ssm block resets counters for the next graph replay (deterministic).
// ---------------------------------------------------------------------------
__global__ __launch_bounds__(128) void k23_fused(
    const float* __restrict__ W_xp,
    const float* __restrict__ W_dt,
    const float* __restrict__ b_dt,
    const float* __restrict__ A_log,
    const float* __restrict__ ssm_state,
    const float* __restrict__ D_param,
    float* __restrict__ new_h_out) {
    const int tid = threadIdx.x;

    if (blockIdx.x < XP_ROWS) {
        // ---- xp row ----
        int wid  = tid >> 5;
        int lane = tid & 31;
        int row  = blockIdx.x;
        const int q4 = D_INNER / 16;  // 512 float4 per quarter-row
        const float4* Wr = reinterpret_cast<const float4*>(W_xp + (size_t)row * D_INNER)
                         + wid * q4;
        const float4* xv = reinterpret_cast<const float4*>(g_xconv) + wid * q4;
        float acc = partial_dot(Wr, xv, lane, q4);

        __shared__ float part[4];
        if (lane == 0) part[wid] = acc;
        __syncthreads();
        if (tid == 0) {
            g_xp[row] = (part[0] + part[1]) + (part[2] + part[3]);
            __threadfence();
            atomicAdd(&c_xp, 1);
        }
        return;
    }

    // ---- ssm block: wait for all 40 xp rows ----
    if (tid == 0) {
        volatile int* vc = (volatile int*)&c_xp;
        while (*vc < XP_ROWS) __nanosleep(64);
    }
    __syncthreads();
    __threadfence();

    __shared__ float s_xp[XP_ROWS];
    if (tid < XP_ROWS) s_xp[tid] = g_xp[tid];
    __syncthreads();

    int i = (blockIdx.x - XP_ROWS) * 128 + tid;

    const float4* wd = reinterpret_cast<const float4*>(W_dt + (size_t)i * DT_RANK);
    float4 w0 = wd[0], w1 = wd[1];
    float acc = b_dt[i]
        + w0.x * s_xp[0] + w0.y * s_xp[1] + w0.z * s_xp[2] + w0.w * s_xp[3]
        + w1.x * s_xp[4] + w1.y * s_xp[5] + w1.z * s_xp[6] + w1.w * s_xp[7];
    float dt = fmaxf(acc, 0.0f) + log1pf(__expf(-fabsf(acc)));

    float xc  = g_xconv[i];
    float dtx = dt * xc;
    const float* B = s_xp + DT_RANK;
    const float* C = s_xp + DT_RANK + D_STATE;

    const float4* Al = reinterpret_cast<const float4*>(A_log + (size_t)i * D_STATE);
    const float4* Hs = reinterpret_cast<const float4*>(ssm_state + (size_t)i * D_STATE);
    float4* Ho = reinterpret_cast<float4*>(new_h_out + (size_t)i * D_STATE);

    float ysum = 0.0f;
    #pragma unroll
    for (int q = 0; q < 4; q++) {
        float4 a4 = Al[q];
        float4 h4 = Hs[q];
        float4 o4;
        o4.x = __expf(-dt * __expf(a4.x)) * h4.x + dtx * B[4 * q + 0];
        o4.y = __expf(-dt * __expf(a4.y)) * h4.y + dtx * B[4 * q + 1];
        o4.z = __expf(-dt * __expf(a4.z)) * h4.z + dtx * B[4 * q + 2];
        o4.w = __expf(-dt * __expf(a4.w)) * h4.w + dtx * B[4 * q + 3];
        ysum += o4.x * C[4 * q + 0] + o4.y * C[4 * q + 1]
              + o4.z * C[4 * q + 2] + o4.w * C[4 * q + 3];
        Ho[q] = o4;
    }

    float yv = ysum + D_param[i] * xc;
    g_y[i] = yv * silu_fast(g_z[i]);

    // counter reset for next replay: last ssm block to finish does it
    __syncthreads();
    if (tid == 0) {
        int d = atomicAdd(&c_done, 1);
        if (d == NB_SSM - 1) {
            c_xp = 0;
            c_done = 0;
            __threadfence();
        }
    }
}

// ---------------------------------------------------------------------------
// K4: out = W_out @ y. (identical to R10 best)
// Block = 128 thr = 4 warps = ONE row (quarter-row / 8 KB per warp).
// ---------------------------------------------------------------------------
__global__ __launch_bounds__(128) void gemv_wout(const float* __restrict__ W,
                                                 float* __restrict__ out) {
    int wid  = threadIdx.x >> 5;
    int lane = threadIdx.x & 31;
    int row  = blockIdx.x;
    const int q4 = D_INNER / 16;  // 512 float4 per quarter-row

    const float4* Wr = reinterpret_cast<const float4*>(W + (size_t)row * D_INNER)
                     + wid * q4;
    const float4* xv = reinterpret_cast<const float4*>(g_y) + wid * q4;

    float acc = partial_dot(Wr, xv, lane, q4);

    __shared__ float part[4];
    if (lane == 0) part[wid] = acc;
    __syncthreads();
    if (threadIdx.x == 0) {
        out[row] = (part[0] + part[1]) + (part[2] + part[3]);
    }
}

// ---------------------------------------------------------------------------
extern "C" void kernel_launch(void* const* d_in, const int* in_sizes, int n_in,
                              void* d_out, int out_size) {
    const float* x           = (const float*)d_in[0];
    const float* ssm_state   = (const float*)d_in[1];
    const float* conv_buffer = (const float*)d_in[2];
    const float* W_in        = (const float*)d_in[3];
    const float* conv_w      = (const float*)d_in[4];
    const float* conv_b      = (const float*)d_in[5];
    const float* W_xp        = (const float*)d_in[6];
    const float* W_dt        = (const float*)d_in[7];
    const float* b_dt        = (const float*)d_in[8];
    const float* A_log       = (const float*)d_in[9];
    const float* D_param     = (const float*)d_in[10];
    const float* W_out       = (const float*)d_in[11];

    float* out   = (float*)d_out;               // [0, 4096)
    float* new_h = (float*)d_out + D_MODEL;     // [4096, 4096 + 8192*16)

    // K1: W_in GEMV + fused conv/SiLU (2 warps/row -> 4096 blocks)
    gemv_win_fused<<<(2 * D_INNER) / 4, 256>>>(W_in, x, conv_buffer, conv_w, conv_b);

    // K23: xp GEMV + ssm update fused (104 blocks, one wave, intra-kernel sync)
    k23_fused<<<NB_K23, 128>>>(W_xp, W_dt, b_dt, A_log, ssm_state, D_param, new_h);

    // K4: out = W_out @ y (1 row per 128-thr block -> 4096 blocks)
    gemv_wout<<<D_MODEL, 128>>>(W_out, out);
}